// round 10
// baseline (speedup 1.0000x reference)
#include <cuda_runtime.h>
#include <cuda_fp16.h>
#include <cstdint>

#define EMBED  512
#define CONVC  512
#define HID    1024
#define LABELS 128
#define M_TOTAL (32 * 1024)

// Scratch (allocation-free rule -> __device__ globals). fp16 payloads.
__device__ __half g_x[(size_t)M_TOTAL * EMBED];   // gathered fp16 embeddings, 32 MB
__device__ __half g_h[(size_t)M_TOTAL * CONVC];   // 32 MB
__device__ __half g_z[(size_t)M_TOTAL * HID];     // 64 MB
__device__ __half g_w0[(size_t)CONVC * EMBED];    // conv_w fp16 [N,K]
__device__ __half g_w1t[(size_t)HID * CONVC];     // w1^T fp16 [1024,512]
__device__ __half g_w2t[(size_t)LABELS * HID];    // w2^T fp16 [128,1024]

__device__ __forceinline__ uint32_t smem_u32(const void* p) {
    uint32_t a;
    asm("{ .reg .u64 t; cvta.to.shared.u64 t, %1; cvt.u32.u64 %0, t; }" : "=r"(a) : "l"(p));
    return a;
}

#define CP_ASYNC16(dst, src) \
    asm volatile("cp.async.cg.shared.global [%0], [%1], 16;" :: "r"(dst), "l"(src))
#define CP_COMMIT() asm volatile("cp.async.commit_group;" ::: "memory")
#define CP_WAIT1()  asm volatile("cp.async.wait_group 1;" ::: "memory")

#define LDSM_X4(r0, r1, r2, r3, addr) \
    asm volatile("ldmatrix.sync.aligned.m8n8.x4.shared.b16 {%0,%1,%2,%3}, [%4];" \
        : "=r"(r0), "=r"(r1), "=r"(r2), "=r"(r3) : "r"(addr))

__device__ __forceinline__ void mma_f16(float* c, const uint32_t* a, const uint32_t* b) {
    asm volatile(
        "mma.sync.aligned.m16n8k16.row.col.f32.f16.f16.f32 "
        "{%0,%1,%2,%3}, {%4,%5,%6,%7}, {%8,%9}, {%0,%1,%2,%3};\n"
        : "+f"(c[0]), "+f"(c[1]), "+f"(c[2]), "+f"(c[3])
        : "r"(a[0]), "r"(a[1]), "r"(a[2]), "r"(a[3]), "r"(b[0]), "r"(b[1]));
}

// ---------------- pipelined fp16 GEMM (ldmatrix fragments) ----------------
// C[M, N_TOTAL] = act(A[M,K] @ Wt[N,K]^T + bias). A, Wt fp16; accumulate fp32.
// BN=128, BK=64 halves. 8 warps (4m x 2n), warp tile (BM/4) x 64. 3-stage ring, 1 sync/chunk.
template <int N_TOTAL, int K, int BM, bool RELU, bool HALF_OUT>
__global__ __launch_bounds__(256, 1)
void gemm_pipe_h(const __half* __restrict__ A, const __half* __restrict__ Wt,
                 const float* __restrict__ bias, void* __restrict__ Cv) {
    constexpr int BN = 128, BK = 64;               // BK in halves = 128 B
    constexpr int KCH = K / BK;
    constexpr int MI  = BM / 64;                   // m16-frags per warp (4 @BM=256, 2 @BM=128)
    constexpr int P32 = 36;                        // u32 per smem row (72 halves, pad 8)
    constexpr int ROWB = P32 * 4;                  // 144 bytes
    constexpr int A_BYTES = BM * ROWB;
    constexpr int B_BYTES = BN * ROWB;
    constexpr int STAGE = A_BYTES + B_BYTES;

    extern __shared__ char smem[];
    const uint32_t sb = smem_u32(smem);

    const int tid  = threadIdx.x;
    const int warp = tid >> 5, lane = tid & 31;
    const int grp  = lane >> 2, tig = lane & 3;
    const int wm   = warp >> 1, wn = warp & 1;

    const int bm = blockIdx.y * BM;
    const int bn = blockIdx.x * BN;

    // ldmatrix per-lane byte offsets
    const int j  = lane >> 3;                      // 0..3
    const int r8 = lane & 7;
    uint32_t offA[MI], offB[4];
#pragma unroll
    for (int mi = 0; mi < MI; mi++)                // A: x4 = (m0-7,k0-7)(m8-15,k0-7)(m0-7,k8-15)(m8-15,k8-15)
        offA[mi] = (uint32_t)((wm * (BM / 4) + mi * 16 + (j & 1) * 8 + r8) * ROWB + (j >> 1) * 16);
#pragma unroll
    for (int p = 0; p < 4; p++)                    // B pair: (n_2p,k0-7)(n_2p,k8-15)(n_2p+1,k0-7)(n_2p+1,k8-15)
        offB[p] = (uint32_t)((wn * 64 + p * 16 + ((lane >> 4) & 1) * 8 + r8) * ROWB + ((lane >> 3) & 1) * 16);

    // stage fill: A BM rows x 8 chunks(16B), B 128 rows x 8 chunks
    auto issue = [&](int s, int kt) {
        const int k0 = kt * BK;
        const uint32_t ab = sb + s * STAGE;
        const uint32_t bb = ab + A_BYTES;
#pragma unroll
        for (int i = 0; i < BM / 32; i++) {
            int idx = tid + i * 256;
            int r = idx >> 3, c4 = idx & 7;
            CP_ASYNC16(ab + (uint32_t)(r * ROWB + c4 * 16),
                       A + (size_t)(bm + r) * K + k0 + c4 * 8);
        }
#pragma unroll
        for (int i = 0; i < 4; i++) {
            int idx = tid + i * 256;
            int r = idx >> 3, c4 = idx & 7;
            CP_ASYNC16(bb + (uint32_t)(r * ROWB + c4 * 16),
                       Wt + (size_t)(bn + r) * K + k0 + c4 * 8);
        }
    };

    float acc[MI][8][4];
#pragma unroll
    for (int mi = 0; mi < MI; mi++)
#pragma unroll
        for (int ni = 0; ni < 8; ni++)
#pragma unroll
            for (int q = 0; q < 4; q++) acc[mi][ni][q] = 0.0f;

    issue(0, 0); CP_COMMIT();
    issue(1, 1); CP_COMMIT();

    for (int kt = 0; kt < KCH; kt++) {
        const int s = kt % 3;
        CP_WAIT1();                                 // stage kt landed
        __syncthreads();                            // also proves stage kt-1 fully consumed
        if (kt + 2 < KCH) issue((kt + 2) % 3, kt + 2);
        CP_COMMIT();

        const uint32_t sA = sb + s * STAGE;
        const uint32_t sB = sA + A_BYTES;
#pragma unroll
        for (int ks = 0; ks < 4; ks++) {            // 4 x k16 steps, +32B each
            const int kb = ks * 32;
            uint32_t a[MI][4], b[8][2];
#pragma unroll
            for (int mi = 0; mi < MI; mi++)
                LDSM_X4(a[mi][0], a[mi][1], a[mi][2], a[mi][3], sA + offA[mi] + kb);
#pragma unroll
            for (int p = 0; p < 4; p++)
                LDSM_X4(b[2 * p][0], b[2 * p][1], b[2 * p + 1][0], b[2 * p + 1][1],
                        sB + offB[p] + kb);
#pragma unroll
            for (int mi = 0; mi < MI; mi++)
#pragma unroll
                for (int ni = 0; ni < 8; ni++)
                    mma_f16(acc[mi][ni], a[mi], b[ni]);
        }
    }

    __syncthreads();
    // Epilogue: bias (+relu); store fp16 (chained) or fp32 (final)
#pragma unroll
    for (int ni = 0; ni < 8; ni++) {
        const int n = bn + wn * 64 + ni * 8 + tig * 2;
        const float bv0 = __ldg(&bias[n]);
        const float bv1 = __ldg(&bias[n + 1]);
#pragma unroll
        for (int mi = 0; mi < MI; mi++) {
            const int m0 = bm + wm * (BM / 4) + mi * 16 + grp;
            float v0 = acc[mi][ni][0] + bv0;
            float v1 = acc[mi][ni][1] + bv1;
            float v2 = acc[mi][ni][2] + bv0;
            float v3 = acc[mi][ni][3] + bv1;
            if (RELU) {
                v0 = fmaxf(v0, 0.0f); v1 = fmaxf(v1, 0.0f);
                v2 = fmaxf(v2, 0.0f); v3 = fmaxf(v3, 0.0f);
            }
            if (HALF_OUT) {
                __half* C = (__half*)Cv;
                *(__half2*)(C + (size_t)m0 * N_TOTAL + n)       = __floats2half2_rn(v0, v1);
                *(__half2*)(C + (size_t)(m0 + 8) * N_TOTAL + n) = __floats2half2_rn(v2, v3);
            } else {
                float* C = (float*)Cv;
                *(float2*)(C + (size_t)m0 * N_TOTAL + n)       = make_float2(v0, v1);
                *(float2*)(C + (size_t)(m0 + 8) * N_TOTAL + n) = make_float2(v2, v3);
            }
        }
    }
}

// ---------------- prep kernels ----------------
__global__ __launch_bounds__(256)
void gather_h_kernel(const int* __restrict__ tok, const float* __restrict__ emb,
                     __half* __restrict__ out) {
    const int i4 = blockIdx.x * 256 + threadIdx.x;
    const int row = i4 >> 7;
    const int c   = (i4 & 127) << 2;
    const float4 v = *(const float4*)(emb + (size_t)tok[row] * EMBED + c);
    __half2 h0 = __floats2half2_rn(v.x, v.y);
    __half2 h1 = __floats2half2_rn(v.z, v.w);
    *(uint2*)(out + (size_t)row * EMBED + c) = make_uint2(*(uint32_t*)&h0, *(uint32_t*)&h1);
}

__global__ __launch_bounds__(256)
void cvt_h_kernel(const float* __restrict__ in, __half* __restrict__ out) {
    const int i4 = blockIdx.x * 256 + threadIdx.x;
    const float4 v = *(const float4*)(in + (size_t)i4 * 4);
    __half2 h0 = __floats2half2_rn(v.x, v.y);
    __half2 h1 = __floats2half2_rn(v.z, v.w);
    *(uint2*)(out + (size_t)i4 * 4) = make_uint2(*(uint32_t*)&h0, *(uint32_t*)&h1);
}

__global__ void transpose_h_kernel(const float* __restrict__ in, __half* __restrict__ out,
                                   int R, int Ccols) {
    __shared__ float t[32][33];
    int bx = blockIdx.x * 32, by = blockIdx.y * 32;
    int x = bx + threadIdx.x;
#pragma unroll
    for (int jj = 0; jj < 32; jj += 8) {
        int y = by + threadIdx.y + jj;
        t[threadIdx.y + jj][threadIdx.x] = in[(size_t)y * Ccols + x];
    }
    __syncthreads();
    x = by + threadIdx.x;
#pragma unroll
    for (int jj = 0; jj < 32; jj += 8) {
        int y = bx + threadIdx.y + jj;
        out[(size_t)y * R + x] = __float2half_rn(t[threadIdx.x][threadIdx.y + jj]);
    }
}

extern "C" void kernel_launch(void* const* d_in, const int* in_sizes, int n_in,
                              void* d_out, int out_size) {
    const int*   tok    = (const int*)d_in[0];
    const float* emb    = (const float*)d_in[1];
    const float* conv_w = (const float*)d_in[2];   // [CONVC, EMBED] = [N,K]
    const float* conv_b = (const float*)d_in[3];
    const float* w1     = (const float*)d_in[4];   // [CONVC, HID]
    const float* b1     = (const float*)d_in[5];
    const float* w2     = (const float*)d_in[6];   // [HID, LABELS]
    const float* b2     = (const float*)d_in[7];
    float* out = (float*)d_out;

    __half *x_buf, *h_buf, *z_buf, *w0, *w1t, *w2t;
    cudaGetSymbolAddress((void**)&x_buf, g_x);
    cudaGetSymbolAddress((void**)&h_buf, g_h);
    cudaGetSymbolAddress((void**)&z_buf, g_z);
    cudaGetSymbolAddress((void**)&w0,  g_w0);
    cudaGetSymbolAddress((void**)&w1t, g_w1t);
    cudaGetSymbolAddress((void**)&w2t, g_w2t);

    constexpr int SMEM256 = 3 * (256 * 144 + 128 * 144);   // 165888
    constexpr int SMEM128 = 3 * (128 * 144 + 128 * 144);   // 110592
    cudaFuncSetAttribute(gemm_pipe_h<CONVC, EMBED, 256, true,  true>,
                         cudaFuncAttributeMaxDynamicSharedMemorySize, SMEM256);
    cudaFuncSetAttribute(gemm_pipe_h<HID, CONVC, 256, true,  true>,
                         cudaFuncAttributeMaxDynamicSharedMemorySize, SMEM256);
    cudaFuncSetAttribute(gemm_pipe_h<LABELS, HID, 128, false, false>,
                         cudaFuncAttributeMaxDynamicSharedMemorySize, SMEM128);

    // Prep (bandwidth-trivial)
    gather_h_kernel<<<(M_TOTAL * EMBED / 4) / 256, 256>>>(tok, emb, x_buf);
    cvt_h_kernel<<<(CONVC * EMBED / 4) / 256, 256>>>(conv_w, w0);
    transpose_h_kernel<<<dim3(HID / 32, CONVC / 32), dim3(32, 8)>>>(w1, w1t, CONVC, HID);
    transpose_h_kernel<<<dim3(LABELS / 32, HID / 32), dim3(32, 8)>>>(w2, w2t, HID, LABELS);

    // GEMM1: h = fp16(relu(x @ conv_w^T + conv_b))    [32768, 512]
    gemm_pipe_h<CONVC, EMBED, 256, true, true>
        <<<dim3(CONVC / 128, M_TOTAL / 256), 256, SMEM256>>>(x_buf, w0, conv_b, h_buf);
    // GEMM2: z = fp16(relu(h @ w1 + b1))              [32768, 1024]
    gemm_pipe_h<HID, CONVC, 256, true, true>
        <<<dim3(HID / 128, M_TOTAL / 256), 256, SMEM256>>>(h_buf, w1t, b1, z_buf);
    // GEMM3: out = z @ w2 + b2                        [32768, 128]
    gemm_pipe_h<LABELS, HID, 128, false, false>
        <<<dim3(LABELS / 128, M_TOTAL / 128), 256, SMEM128>>>(z_buf, w2t, b2, out);
}

// round 11
// speedup vs baseline: 1.1059x; 1.1059x over previous
#include <cuda_runtime.h>
#include <cuda_fp16.h>
#include <cstdint>

#define EMBED  512
#define CONVC  512
#define HID    1024
#define LABELS 128
#define M_TOTAL (32 * 1024)

// Scratch (allocation-free rule -> __device__ globals). fp16 payloads.
__device__ __half g_x[(size_t)M_TOTAL * EMBED];   // gathered fp16 embeddings, 32 MB
__device__ __half g_h[(size_t)M_TOTAL * CONVC];   // 32 MB
__device__ __half g_z[(size_t)M_TOTAL * HID];     // 64 MB
__device__ __half g_w0[(size_t)CONVC * EMBED];    // conv_w fp16 [N,K]
__device__ __half g_w1t[(size_t)HID * CONVC];     // w1^T fp16 [1024,512]
__device__ __half g_w2t[(size_t)LABELS * HID];    // w2^T fp16 [128,1024]

__device__ __forceinline__ uint32_t smem_u32(const void* p) {
    uint32_t a;
    asm("{ .reg .u64 t; cvta.to.shared.u64 t, %1; cvt.u32.u64 %0, t; }" : "=r"(a) : "l"(p));
    return a;
}

#define CP_ASYNC16(dst, src) \
    asm volatile("cp.async.cg.shared.global [%0], [%1], 16;" :: "r"(dst), "l"(src))
#define CP_COMMIT() asm volatile("cp.async.commit_group;" ::: "memory")
#define CP_WAIT1()  asm volatile("cp.async.wait_group 1;" ::: "memory")

#define LDSM_X4(r0, r1, r2, r3, addr) \
    asm volatile("ldmatrix.sync.aligned.m8n8.x4.shared.b16 {%0,%1,%2,%3}, [%4];" \
        : "=r"(r0), "=r"(r1), "=r"(r2), "=r"(r3) : "r"(addr))

__device__ __forceinline__ void mma_f16(float* c, const uint32_t* a, const uint32_t* b) {
    asm volatile(
        "mma.sync.aligned.m16n8k16.row.col.f32.f16.f16.f32 "
        "{%0,%1,%2,%3}, {%4,%5,%6,%7}, {%8,%9}, {%0,%1,%2,%3};\n"
        : "+f"(c[0]), "+f"(c[1]), "+f"(c[2]), "+f"(c[3])
        : "r"(a[0]), "r"(a[1]), "r"(a[2]), "r"(a[3]), "r"(b[0]), "r"(b[1]));
}

// ---------------- pipelined fp16 GEMM, 2 CTAs/SM ----------------
// C[M, N_TOTAL] = act(A[M,K] @ Wt[N,K]^T + bias). A, Wt fp16; accumulate fp32.
// BM=128, BN=128, BK=64 halves. 8 warps (4m x 2n), warp tile 32x64.
// 3-stage cp.async ring, single sync per chunk. __launch_bounds__(256, 2).
template <int N_TOTAL, int K, bool RELU, bool HALF_OUT>
__global__ __launch_bounds__(256, 2)
void gemm_pipe_h(const __half* __restrict__ A, const __half* __restrict__ Wt,
                 const float* __restrict__ bias, void* __restrict__ Cv) {
    constexpr int BM = 128, BN = 128, BK = 64;     // BK in halves = 128 B
    constexpr int KCH = K / BK;
    constexpr int MI  = 2;                          // m16-frags per warp (32 rows)
    constexpr int P32 = 36;                         // u32 per smem row (72 halves, pad 8)
    constexpr int ROWB = P32 * 4;                   // 144 bytes
    constexpr int A_BYTES = BM * ROWB;              // 18432
    constexpr int B_BYTES = BN * ROWB;              // 18432
    constexpr int STAGE = A_BYTES + B_BYTES;        // 36864 (x3 = 110592)

    extern __shared__ char smem[];
    const uint32_t sb = smem_u32(smem);

    const int tid  = threadIdx.x;
    const int warp = tid >> 5, lane = tid & 31;
    const int grp  = lane >> 2, tig = lane & 3;
    const int wm   = warp >> 1, wn = warp & 1;

    const int bm = blockIdx.y * BM;
    const int bn = blockIdx.x * BN;

    // ldmatrix per-lane byte offsets
    const int j  = lane >> 3;                       // 0..3
    const int r8 = lane & 7;
    uint32_t offA[MI], offB[4];
#pragma unroll
    for (int mi = 0; mi < MI; mi++)                 // A x4: (m0-7,k0-7)(m8-15,k0-7)(m0-7,k8-15)(m8-15,k8-15)
        offA[mi] = (uint32_t)((wm * 32 + mi * 16 + (j & 1) * 8 + r8) * ROWB + (j >> 1) * 16);
#pragma unroll
    for (int p = 0; p < 4; p++)                     // B pair: n-frags 2p, 2p+1
        offB[p] = (uint32_t)((wn * 64 + p * 16 + ((lane >> 4) & 1) * 8 + r8) * ROWB + ((lane >> 3) & 1) * 16);

    // stage fill: A 128 rows x 8 chunks(16B) = 4/thread, B same
    auto issue = [&](int s, int kt) {
        const int k0 = kt * BK;
        const uint32_t ab = sb + s * STAGE;
        const uint32_t bb = ab + A_BYTES;
#pragma unroll
        for (int i = 0; i < 4; i++) {
            int idx = tid + i * 256;
            int r = idx >> 3, c4 = idx & 7;
            CP_ASYNC16(ab + (uint32_t)(r * ROWB + c4 * 16),
                       A + (size_t)(bm + r) * K + k0 + c4 * 8);
        }
#pragma unroll
        for (int i = 0; i < 4; i++) {
            int idx = tid + i * 256;
            int r = idx >> 3, c4 = idx & 7;
            CP_ASYNC16(bb + (uint32_t)(r * ROWB + c4 * 16),
                       Wt + (size_t)(bn + r) * K + k0 + c4 * 8);
        }
    };

    float acc[MI][8][4];
#pragma unroll
    for (int mi = 0; mi < MI; mi++)
#pragma unroll
        for (int ni = 0; ni < 8; ni++)
#pragma unroll
            for (int q = 0; q < 4; q++) acc[mi][ni][q] = 0.0f;

    issue(0, 0); CP_COMMIT();
    issue(1, 1); CP_COMMIT();

    for (int kt = 0; kt < KCH; kt++) {
        const int s = kt % 3;
        CP_WAIT1();                                 // stage kt landed
        __syncthreads();                            // also proves stage kt-1 consumed
        if (kt + 2 < KCH) issue((kt + 2) % 3, kt + 2);
        CP_COMMIT();

        const uint32_t sA = sb + s * STAGE;
        const uint32_t sB = sA + A_BYTES;
#pragma unroll
        for (int ks = 0; ks < 4; ks++) {            // 4 x k16 steps, +32B each
            const int kb = ks * 32;
            uint32_t a[MI][4], b[8][2];
#pragma unroll
            for (int mi = 0; mi < MI; mi++)
                LDSM_X4(a[mi][0], a[mi][1], a[mi][2], a[mi][3], sA + offA[mi] + kb);
#pragma unroll
            for (int p = 0; p < 4; p++)
                LDSM_X4(b[2 * p][0], b[2 * p][1], b[2 * p + 1][0], b[2 * p + 1][1],
                        sB + offB[p] + kb);
#pragma unroll
            for (int mi = 0; mi < MI; mi++)
#pragma unroll
                for (int ni = 0; ni < 8; ni++)
                    mma_f16(acc[mi][ni], a[mi], b[ni]);
        }
    }

    __syncthreads();
    // Epilogue: bias (+relu); store fp16 (chained) or fp32 (final)
#pragma unroll
    for (int ni = 0; ni < 8; ni++) {
        const int n = bn + wn * 64 + ni * 8 + tig * 2;
        const float bv0 = __ldg(&bias[n]);
        const float bv1 = __ldg(&bias[n + 1]);
#pragma unroll
        for (int mi = 0; mi < MI; mi++) {
            const int m0 = bm + wm * 32 + mi * 16 + grp;
            float v0 = acc[mi][ni][0] + bv0;
            float v1 = acc[mi][ni][1] + bv1;
            float v2 = acc[mi][ni][2] + bv0;
            float v3 = acc[mi][ni][3] + bv1;
            if (RELU) {
                v0 = fmaxf(v0, 0.0f); v1 = fmaxf(v1, 0.0f);
                v2 = fmaxf(v2, 0.0f); v3 = fmaxf(v3, 0.0f);
            }
            if (HALF_OUT) {
                __half* C = (__half*)Cv;
                *(__half2*)(C + (size_t)m0 * N_TOTAL + n)       = __floats2half2_rn(v0, v1);
                *(__half2*)(C + (size_t)(m0 + 8) * N_TOTAL + n) = __floats2half2_rn(v2, v3);
            } else {
                float* C = (float*)Cv;
                *(float2*)(C + (size_t)m0 * N_TOTAL + n)       = make_float2(v0, v1);
                *(float2*)(C + (size_t)(m0 + 8) * N_TOTAL + n) = make_float2(v2, v3);
            }
        }
    }
}

// ---------------- prep kernels ----------------
__global__ __launch_bounds__(256)
void gather_h_kernel(const int* __restrict__ tok, const float* __restrict__ emb,
                     __half* __restrict__ out) {
    const int i4 = blockIdx.x * 256 + threadIdx.x;
    const int row = i4 >> 7;
    const int c   = (i4 & 127) << 2;
    const float4 v = *(const float4*)(emb + (size_t)tok[row] * EMBED + c);
    __half2 h0 = __floats2half2_rn(v.x, v.y);
    __half2 h1 = __floats2half2_rn(v.z, v.w);
    *(uint2*)(out + (size_t)row * EMBED + c) = make_uint2(*(uint32_t*)&h0, *(uint32_t*)&h1);
}

__global__ __launch_bounds__(256)
void cvt_h_kernel(const float* __restrict__ in, __half* __restrict__ out) {
    const int i4 = blockIdx.x * 256 + threadIdx.x;
    const float4 v = *(const float4*)(in + (size_t)i4 * 4);
    __half2 h0 = __floats2half2_rn(v.x, v.y);
    __half2 h1 = __floats2half2_rn(v.z, v.w);
    *(uint2*)(out + (size_t)i4 * 4) = make_uint2(*(uint32_t*)&h0, *(uint32_t*)&h1);
}

__global__ void transpose_h_kernel(const float* __restrict__ in, __half* __restrict__ out,
                                   int R, int Ccols) {
    __shared__ float t[32][33];
    int bx = blockIdx.x * 32, by = blockIdx.y * 32;
    int x = bx + threadIdx.x;
#pragma unroll
    for (int jj = 0; jj < 32; jj += 8) {
        int y = by + threadIdx.y + jj;
        t[threadIdx.y + jj][threadIdx.x] = in[(size_t)y * Ccols + x];
    }
    __syncthreads();
    x = by + threadIdx.x;
#pragma unroll
    for (int jj = 0; jj < 32; jj += 8) {
        int y = bx + threadIdx.y + jj;
        out[(size_t)y * R + x] = __float2half_rn(t[threadIdx.x][threadIdx.y + jj]);
    }
}

extern "C" void kernel_launch(void* const* d_in, const int* in_sizes, int n_in,
                              void* d_out, int out_size) {
    const int*   tok    = (const int*)d_in[0];
    const float* emb    = (const float*)d_in[1];
    const float* conv_w = (const float*)d_in[2];   // [CONVC, EMBED] = [N,K]
    const float* conv_b = (const float*)d_in[3];
    const float* w1     = (const float*)d_in[4];   // [CONVC, HID]
    const float* b1     = (const float*)d_in[5];
    const float* w2     = (const float*)d_in[6];   // [HID, LABELS]
    const float* b2     = (const float*)d_in[7];
    float* out = (float*)d_out;

    __half *x_buf, *h_buf, *z_buf, *w0, *w1t, *w2t;
    cudaGetSymbolAddress((void**)&x_buf, g_x);
    cudaGetSymbolAddress((void**)&h_buf, g_h);
    cudaGetSymbolAddress((void**)&z_buf, g_z);
    cudaGetSymbolAddress((void**)&w0,  g_w0);
    cudaGetSymbolAddress((void**)&w1t, g_w1t);
    cudaGetSymbolAddress((void**)&w2t, g_w2t);

    constexpr int SMEM = 3 * (128 * 144 + 128 * 144);   // 110592 -> 2 CTAs/SM
    cudaFuncSetAttribute(gemm_pipe_h<CONVC, EMBED, true,  true>,
                         cudaFuncAttributeMaxDynamicSharedMemorySize, SMEM);
    cudaFuncSetAttribute(gemm_pipe_h<HID, CONVC, true,  true>,
                         cudaFuncAttributeMaxDynamicSharedMemorySize, SMEM);
    cudaFuncSetAttribute(gemm_pipe_h<LABELS, HID, false, false>,
                         cudaFuncAttributeMaxDynamicSharedMemorySize, SMEM);

    // Prep (bandwidth-trivial)
    gather_h_kernel<<<(M_TOTAL * EMBED / 4) / 256, 256>>>(tok, emb, x_buf);
    cvt_h_kernel<<<(CONVC * EMBED / 4) / 256, 256>>>(conv_w, w0);
    transpose_h_kernel<<<dim3(HID / 32, CONVC / 32), dim3(32, 8)>>>(w1, w1t, CONVC, HID);
    transpose_h_kernel<<<dim3(LABELS / 32, HID / 32), dim3(32, 8)>>>(w2, w2t, HID, LABELS);

    // GEMM1: h = fp16(relu(x @ conv_w^T + conv_b))    [32768, 512]
    gemm_pipe_h<CONVC, EMBED, true, true>
        <<<dim3(CONVC / 128, M_TOTAL / 128), 256, SMEM>>>(x_buf, w0, conv_b, h_buf);
    // GEMM2: z = fp16(relu(h @ w1 + b1))              [32768, 1024]
    gemm_pipe_h<HID, CONVC, true, true>
        <<<dim3(HID / 128, M_TOTAL / 128), 256, SMEM>>>(h_buf, w1t, b1, z_buf);
    // GEMM3: out = z @ w2 + b2                        [32768, 128]
    gemm_pipe_h<LABELS, HID, false, false>
        <<<dim3(LABELS / 128, M_TOTAL / 128), 256, SMEM>>>(z_buf, w2t, b2, out);
}

// round 12
// speedup vs baseline: 1.1190x; 1.0119x over previous
#include <cuda_runtime.h>
#include <cuda_fp16.h>
#include <cstdint>

#define EMBED  512
#define CONVC  512
#define HID    1024
#define LABELS 128
#define M_TOTAL (32 * 1024)

// Scratch (allocation-free rule -> __device__ globals). fp16 payloads.
__device__ __half g_x[(size_t)M_TOTAL * EMBED];   // gathered fp16 embeddings, 32 MB
__device__ __half g_h[(size_t)M_TOTAL * CONVC];   // 32 MB
__device__ __half g_z[(size_t)M_TOTAL * HID];     // 64 MB
__device__ __half g_w0[(size_t)CONVC * EMBED];    // conv_w fp16 [N,K]
__device__ __half g_w1t[(size_t)HID * CONVC];     // w1^T fp16 [1024,512]
__device__ __half g_w2t[(size_t)LABELS * HID];    // w2^T fp16 [128,1024]

__device__ __forceinline__ uint32_t smem_u32(const void* p) {
    uint32_t a;
    asm("{ .reg .u64 t; cvta.to.shared.u64 t, %1; cvt.u32.u64 %0, t; }" : "=r"(a) : "l"(p));
    return a;
}

#define CP_ASYNC16(dst, src) \
    asm volatile("cp.async.cg.shared.global [%0], [%1], 16;" :: "r"(dst), "l"(src))
#define CP_COMMIT() asm volatile("cp.async.commit_group;" ::: "memory")
#define CP_WAIT1()  asm volatile("cp.async.wait_group 1;" ::: "memory")
#define CP_WAIT0()  asm volatile("cp.async.wait_group 0;" ::: "memory")

#define LDSM_X4(r0, r1, r2, r3, addr) \
    asm volatile("ldmatrix.sync.aligned.m8n8.x4.shared.b16 {%0,%1,%2,%3}, [%4];" \
        : "=r"(r0), "=r"(r1), "=r"(r2), "=r"(r3) : "r"(addr))

__device__ __forceinline__ void mma_f16(float* c, const uint32_t* a, const uint32_t* b) {
    asm volatile(
        "mma.sync.aligned.m16n8k16.row.col.f32.f16.f16.f32 "
        "{%0,%1,%2,%3}, {%4,%5,%6,%7}, {%8,%9}, {%0,%1,%2,%3};\n"
        : "+f"(c[0]), "+f"(c[1]), "+f"(c[2]), "+f"(c[3])
        : "r"(a[0]), "r"(a[1]), "r"(a[2]), "r"(a[3]), "r"(b[0]), "r"(b[1]));
}

// ---------------- persistent pipelined fp16 GEMM, 2 CTAs/SM ----------------
// C[M, N_TOTAL] = act(A[M,K] @ Wt[N,K]^T + bias). A, Wt fp16; accumulate fp32.
// BM=128, BN=128, BK=64 halves. 8 warps (4m x 2n), warp tile 32x64.
// 3-stage cp.async ring, single sync per chunk. Persistent tile loop (no wave quantization).
template <int N_TOTAL, int K, bool RELU, bool HALF_OUT>
__global__ __launch_bounds__(256, 2)
void gemm_pipe_h(const __half* __restrict__ A, const __half* __restrict__ Wt,
                 const float* __restrict__ bias, void* __restrict__ Cv) {
    constexpr int BM = 128, BN = 128, BK = 64;     // BK in halves = 128 B
    constexpr int KCH = K / BK;
    constexpr int MI  = 2;                          // m16-frags per warp (32 rows)
    constexpr int P32 = 36;                         // u32 per smem row (72 halves, pad 8)
    constexpr int ROWB = P32 * 4;                   // 144 bytes
    constexpr int A_BYTES = BM * ROWB;              // 18432
    constexpr int B_BYTES = BN * ROWB;              // 18432
    constexpr int STAGE = A_BYTES + B_BYTES;        // 36864 (x3 = 110592)
    constexpr int NTX = N_TOTAL / BN;
    constexpr int NTILES = (M_TOTAL / BM) * NTX;

    extern __shared__ char smem[];
    const uint32_t sb = smem_u32(smem);

    const int tid  = threadIdx.x;
    const int warp = tid >> 5, lane = tid & 31;
    const int grp  = lane >> 2, tig = lane & 3;
    const int wm   = warp >> 1, wn = warp & 1;

    // ldmatrix per-lane byte offsets (tile-invariant)
    const int j  = lane >> 3;                       // 0..3
    const int r8 = lane & 7;
    uint32_t offA[MI], offB[4];
#pragma unroll
    for (int mi = 0; mi < MI; mi++)                 // A x4: (m0-7,k0-7)(m8-15,k0-7)(m0-7,k8-15)(m8-15,k8-15)
        offA[mi] = (uint32_t)((wm * 32 + mi * 16 + (j & 1) * 8 + r8) * ROWB + (j >> 1) * 16);
#pragma unroll
    for (int p = 0; p < 4; p++)                     // B pair: n-frags 2p, 2p+1
        offB[p] = (uint32_t)((wn * 64 + p * 16 + ((lane >> 4) & 1) * 8 + r8) * ROWB + ((lane >> 3) & 1) * 16);

    const int ldr = tid >> 3, ldc = tid & 7;        // stage-fill row/col (4 rows-apart x 8 chunks)

    for (int t = blockIdx.x; t < NTILES; t += gridDim.x) {
        const int bm = (t / NTX) * BM;
        const int bn = (t % NTX) * BN;

        auto issue = [&](int s, int kt) {
            const int k0 = kt * BK;
            const uint32_t ab = sb + s * STAGE;
            const uint32_t bb = ab + A_BYTES;
#pragma unroll
            for (int i = 0; i < 4; i++) {
                int r = ldr + i * 32;
                CP_ASYNC16(ab + (uint32_t)(r * ROWB + ldc * 16),
                           A + (size_t)(bm + r) * K + k0 + ldc * 8);
            }
#pragma unroll
            for (int i = 0; i < 4; i++) {
                int r = ldr + i * 32;
                CP_ASYNC16(bb + (uint32_t)(r * ROWB + ldc * 16),
                           Wt + (size_t)(bn + r) * K + k0 + ldc * 8);
            }
        };

        float acc[MI][8][4];
#pragma unroll
        for (int mi = 0; mi < MI; mi++)
#pragma unroll
            for (int ni = 0; ni < 8; ni++)
#pragma unroll
                for (int q = 0; q < 4; q++) acc[mi][ni][q] = 0.0f;

        __syncthreads();                            // prior tile's stage reads done
        issue(0, 0); CP_COMMIT();
        issue(1, 1); CP_COMMIT();

        for (int kt = 0; kt < KCH; kt++) {
            const int s = kt % 3;
            CP_WAIT1();                             // stage kt landed
            __syncthreads();                        // also proves stage kt-1 consumed
            if (kt + 2 < KCH) issue((kt + 2) % 3, kt + 2);
            CP_COMMIT();

            const uint32_t sA = sb + s * STAGE;
            const uint32_t sB = sA + A_BYTES;
#pragma unroll
            for (int ks = 0; ks < 4; ks++) {        // 4 x k16 steps, +32B each
                const int kb = ks * 32;
                uint32_t a[MI][4], b[8][2];
#pragma unroll
                for (int mi = 0; mi < MI; mi++)
                    LDSM_X4(a[mi][0], a[mi][1], a[mi][2], a[mi][3], sA + offA[mi] + kb);
#pragma unroll
                for (int p = 0; p < 4; p++)
                    LDSM_X4(b[2 * p][0], b[2 * p][1], b[2 * p + 1][0], b[2 * p + 1][1],
                            sB + offB[p] + kb);
#pragma unroll
                for (int mi = 0; mi < MI; mi++)
#pragma unroll
                    for (int ni = 0; ni < 8; ni++)
                        mma_f16(acc[mi][ni], a[mi], b[ni]);
            }
        }
        CP_WAIT0();                                 // ring drained before next tile reuses it

        // Epilogue (no smem): bias (+relu); store fp16 (chained) or fp32 (final)
#pragma unroll
        for (int ni = 0; ni < 8; ni++) {
            const int n = bn + wn * 64 + ni * 8 + tig * 2;
            const float bv0 = bias[n];
            const float bv1 = bias[n + 1];
#pragma unroll
            for (int mi = 0; mi < MI; mi++) {
                const int m0 = bm + wm * 32 + mi * 16 + grp;
                float v0 = acc[mi][ni][0] + bv0;
                float v1 = acc[mi][ni][1] + bv1;
                float v2 = acc[mi][ni][2] + bv0;
                float v3 = acc[mi][ni][3] + bv1;
                if (RELU) {
                    v0 = fmaxf(v0, 0.0f); v1 = fmaxf(v1, 0.0f);
                    v2 = fmaxf(v2, 0.0f); v3 = fmaxf(v3, 0.0f);
                }
                if (HALF_OUT) {
                    __half* C = (__half*)Cv;
                    *(__half2*)(C + (size_t)m0 * N_TOTAL + n)       = __floats2half2_rn(v0, v1);
                    *(__half2*)(C + (size_t)(m0 + 8) * N_TOTAL + n) = __floats2half2_rn(v2, v3);
                } else {
                    float* C = (float*)Cv;
                    *(float2*)(C + (size_t)m0 * N_TOTAL + n)       = make_float2(v0, v1);
                    *(float2*)(C + (size_t)(m0 + 8) * N_TOTAL + n) = make_float2(v2, v3);
                }
            }
        }
    }
}

// ---------------- prep kernels ----------------
// Gather embedding rows -> fp16: 2 float4 per thread
__global__ __launch_bounds__(256)
void gather_h_kernel(const int* __restrict__ tok, const float* __restrict__ emb,
                     __half* __restrict__ out) {
    const int base = (blockIdx.x * 256 + threadIdx.x) * 2;
#pragma unroll
    for (int u = 0; u < 2; u++) {
        const int i4 = base + u;
        const int row = i4 >> 7;                    // EMBED/4 = 128
        const int c   = (i4 & 127) << 2;
        const float4 v = *(const float4*)(emb + (size_t)tok[row] * EMBED + c);
        __half2 h0 = __floats2half2_rn(v.x, v.y);
        __half2 h1 = __floats2half2_rn(v.z, v.w);
        *(uint2*)(out + (size_t)row * EMBED + c) = make_uint2(*(uint32_t*)&h0, *(uint32_t*)&h1);
    }
}

// Merged weight prep: [0,256) cvt w0; [256,768) transpose w1; [768,896) transpose w2
__global__ __launch_bounds__(256)
void weights_prep_kernel(const float* __restrict__ conv_w, __half* __restrict__ w0,
                         const float* __restrict__ w1, __half* __restrict__ w1t,
                         const float* __restrict__ w2, __half* __restrict__ w2t) {
    const int b = blockIdx.x;
    const int tid = threadIdx.x;
    if (b < 256) {                                  // cvt conv_w: 256 blocks x 256 float4
        const int i4 = b * 256 + tid;
        const float4 v = *(const float4*)(conv_w + (size_t)i4 * 4);
        __half2 h0 = __floats2half2_rn(v.x, v.y);
        __half2 h1 = __floats2half2_rn(v.z, v.w);
        *(uint2*)(w0 + (size_t)i4 * 4) = make_uint2(*(uint32_t*)&h0, *(uint32_t*)&h1);
        return;
    }
    // transpose section
    const float* in; __half* outp; int R, Ccols, tb;
    if (b < 768) { in = w1; outp = w1t; R = CONVC; Ccols = HID; tb = b - 256; }   // 32x16 tiles
    else         { in = w2; outp = w2t; R = HID;   Ccols = LABELS; tb = b - 768; } // 4x32 tiles
    const int tpr = Ccols / 32;                     // tiles per row of input
    const int by = (tb / tpr) * 32, bx = (tb % tpr) * 32;
    const int tx = tid & 31, ty = tid >> 5;         // 32 x 8
    __shared__ float t[32][33];
    int x = bx + tx;
#pragma unroll
    for (int jj = 0; jj < 32; jj += 8) {
        int y = by + ty + jj;
        t[ty + jj][tx] = in[(size_t)y * Ccols + x];
    }
    __syncthreads();
    x = by + tx;
#pragma unroll
    for (int jj = 0; jj < 32; jj += 8) {
        int y = bx + ty + jj;
        outp[(size_t)y * R + x] = __float2half_rn(t[tx][ty + jj]);
    }
}

extern "C" void kernel_launch(void* const* d_in, const int* in_sizes, int n_in,
                              void* d_out, int out_size) {
    const int*   tok    = (const int*)d_in[0];
    const float* emb    = (const float*)d_in[1];
    const float* conv_w = (const float*)d_in[2];   // [CONVC, EMBED] = [N,K]
    const float* conv_b = (const float*)d_in[3];
    const float* w1     = (const float*)d_in[4];   // [CONVC, HID]
    const float* b1     = (const float*)d_in[5];
    const float* w2     = (const float*)d_in[6];   // [HID, LABELS]
    const float* b2     = (const float*)d_in[7];
    float* out = (float*)d_out;

    __half *x_buf, *h_buf, *z_buf, *w0, *w1t, *w2t;
    cudaGetSymbolAddress((void**)&x_buf, g_x);
    cudaGetSymbolAddress((void**)&h_buf, g_h);
    cudaGetSymbolAddress((void**)&z_buf, g_z);
    cudaGetSymbolAddress((void**)&w0,  g_w0);
    cudaGetSymbolAddress((void**)&w1t, g_w1t);
    cudaGetSymbolAddress((void**)&w2t, g_w2t);

    constexpr int SMEM = 3 * (128 * 144 + 128 * 144);   // 110592 -> 2 CTAs/SM
    cudaFuncSetAttribute(gemm_pipe_h<CONVC, EMBED, true,  true>,
                         cudaFuncAttributeMaxDynamicSharedMemorySize, SMEM);
    cudaFuncSetAttribute(gemm_pipe_h<HID, CONVC, true,  true>,
                         cudaFuncAttributeMaxDynamicSharedMemorySize, SMEM);
    cudaFuncSetAttribute(gemm_pipe_h<LABELS, HID, false, false>,
                         cudaFuncAttributeMaxDynamicSharedMemorySize, SMEM);

    constexpr int PERSIST = 296;                    // 148 SMs x 2 CTAs

    // Prep
    gather_h_kernel<<<(M_TOTAL * EMBED / 8) / 256, 256>>>(tok, emb, x_buf);
    weights_prep_kernel<<<896, 256>>>(conv_w, w0, w1, w1t, w2, w2t);

    // GEMM1: h = fp16(relu(x @ conv_w^T + conv_b))    [32768, 512], 1024 tiles
    gemm_pipe_h<CONVC, EMBED, true, true>
        <<<PERSIST, 256, SMEM>>>(x_buf, w0, conv_b, h_buf);
    // GEMM2: z = fp16(relu(h @ w1 + b1))              [32768, 1024], 2048 tiles
    gemm_pipe_h<HID, CONVC, true, true>
        <<<PERSIST, 256, SMEM>>>(h_buf, w1t, b1, z_buf);
    // GEMM3: out = z @ w2 + b2                        [32768, 128], 256 tiles
    gemm_pipe_h<LABELS, HID, false, false>
        <<<256, 256, SMEM>>>(z_buf, w2t, b2, out);
}

// round 13
// speedup vs baseline: 1.1689x; 1.0446x over previous
#include <cuda_runtime.h>
#include <cuda_fp16.h>
#include <cstdint>

#define EMBED  512
#define CONVC  512
#define HID    1024
#define LABELS 128
#define M_TOTAL (32 * 1024)

// Scratch (allocation-free rule -> __device__ globals). fp16 payloads.
__device__ __half g_x[(size_t)M_TOTAL * EMBED];   // gathered fp16 embeddings, 32 MB
__device__ __half g_h[(size_t)M_TOTAL * CONVC];   // 32 MB
__device__ __half g_z[(size_t)M_TOTAL * HID];     // 64 MB
__device__ __half g_w0[(size_t)CONVC * EMBED];    // conv_w fp16 [N,K]
__device__ __half g_w1t[(size_t)HID * CONVC];     // w1^T fp16 [1024,512]
__device__ __half g_w2t[(size_t)LABELS * HID];    // w2^T fp16 [128,1024]

__device__ __forceinline__ uint32_t smem_u32(const void* p) {
    uint32_t a;
    asm("{ .reg .u64 t; cvta.to.shared.u64 t, %1; cvt.u32.u64 %0, t; }" : "=r"(a) : "l"(p));
    return a;
}

#define CP_ASYNC16(dst, src) \
    asm volatile("cp.async.cg.shared.global [%0], [%1], 16;" :: "r"(dst), "l"(src))
#define CP_COMMIT() asm volatile("cp.async.commit_group;" ::: "memory")
#define CP_WAIT1()  asm volatile("cp.async.wait_group 1;" ::: "memory")

#define LDSM_X4(r0, r1, r2, r3, addr) \
    asm volatile("ldmatrix.sync.aligned.m8n8.x4.shared.b16 {%0,%1,%2,%3}, [%4];" \
        : "=r"(r0), "=r"(r1), "=r"(r2), "=r"(r3) : "r"(addr))

__device__ __forceinline__ void mma_f16(float* c, const uint32_t* a, const uint32_t* b) {
    asm volatile(
        "mma.sync.aligned.m16n8k16.row.col.f32.f16.f16.f32 "
        "{%0,%1,%2,%3}, {%4,%5,%6,%7}, {%8,%9}, {%0,%1,%2,%3};\n"
        : "+f"(c[0]), "+f"(c[1]), "+f"(c[2]), "+f"(c[3])
        : "r"(a[0]), "r"(a[1]), "r"(a[2]), "r"(a[3]), "r"(b[0]), "r"(b[1]));
}

// ---------- continuous-ring persistent fp16 GEMM, 2 CTAs/SM ----------
// C[M, N_TOTAL] = act(A[M,K] @ Wt[N,K]^T + bias). A, Wt fp16; accumulate fp32.
// BM=128, BN=128, BK=64 halves. 8 warps (4m x 2n), warp tile 32x64.
// All (tile, chunk) pairs per CTA form ONE chunk stream over a 3-stage cp.async
// ring: no per-tile drain/refill; epilogue overlaps next tile's loads.
template <int N_TOTAL, int K, bool RELU, bool HALF_OUT>
__global__ __launch_bounds__(256, 2)
void gemm_pipe_h(const __half* __restrict__ A, const __half* __restrict__ Wt,
                 const float* __restrict__ bias, void* __restrict__ Cv) {
    constexpr int BM = 128, BN = 128, BK = 64;     // BK in halves = 128 B
    constexpr int KCH = K / BK;
    constexpr int MI  = 2;                          // m16-frags per warp (32 rows)
    constexpr int P32 = 36;                         // u32 per smem row (72 halves, pad 8)
    constexpr int ROWB = P32 * 4;                   // 144 bytes
    constexpr int A_BYTES = BM * ROWB;              // 18432
    constexpr int B_BYTES = BN * ROWB;              // 18432
    constexpr int STAGE = A_BYTES + B_BYTES;        // 36864 (x3 = 110592)
    constexpr int NTX = N_TOTAL / BN;
    constexpr int NTILES = (M_TOTAL / BM) * NTX;

    extern __shared__ char smem[];
    const uint32_t sb = smem_u32(smem);

    const int tid  = threadIdx.x;
    const int warp = tid >> 5, lane = tid & 31;
    const int grp  = lane >> 2, tig = lane & 3;
    const int wm   = warp >> 1, wn = warp & 1;

    // ldmatrix per-lane byte offsets (tile-invariant)
    const int j  = lane >> 3;                       // 0..3
    const int r8 = lane & 7;
    uint32_t offA[MI], offB[4];
#pragma unroll
    for (int mi = 0; mi < MI; mi++)                 // A x4: (m0-7,k0-7)(m8-15,k0-7)(m0-7,k8-15)(m8-15,k8-15)
        offA[mi] = (uint32_t)((wm * 32 + mi * 16 + (j & 1) * 8 + r8) * ROWB + (j >> 1) * 16);
#pragma unroll
    for (int p = 0; p < 4; p++)                     // B pair: n-frags 2p, 2p+1
        offB[p] = (uint32_t)((wn * 64 + p * 16 + ((lane >> 4) & 1) * 8 + r8) * ROWB + ((lane >> 3) & 1) * 16);

    const int ldr = tid >> 3, ldc = tid & 7;        // stage-fill row/col

    // issue chunk c (global per-CTA chunk stream index) into ring stage c%3
    auto issue = [&](int c) {
        const int t  = blockIdx.x + (c / KCH) * gridDim.x;
        if (t >= NTILES) return;
        const int kt = c % KCH;
        const int bm = (t / NTX) * BM;
        const int bn = (t % NTX) * BN;
        const int k0 = kt * BK;
        const uint32_t ab = sb + (c % 3) * STAGE;
        const uint32_t bb = ab + A_BYTES;
#pragma unroll
        for (int i = 0; i < 4; i++) {
            int r = ldr + i * 32;
            CP_ASYNC16(ab + (uint32_t)(r * ROWB + ldc * 16),
                       A + (size_t)(bm + r) * K + k0 + ldc * 8);
        }
#pragma unroll
        for (int i = 0; i < 4; i++) {
            int r = ldr + i * 32;
            CP_ASYNC16(bb + (uint32_t)(r * ROWB + ldc * 16),
                       Wt + (size_t)(bn + r) * K + k0 + ldc * 8);
        }
    };

    // per-CTA tile count and total chunk stream length
    const int my_tiles = (NTILES - blockIdx.x + (int)gridDim.x - 1) / (int)gridDim.x;
    const int nch = my_tiles * KCH;
    if (nch == 0) return;

    float acc[MI][8][4];
#pragma unroll
    for (int mi = 0; mi < MI; mi++)
#pragma unroll
        for (int ni = 0; ni < 8; ni++)
#pragma unroll
            for (int q = 0; q < 4; q++) acc[mi][ni][q] = 0.0f;

    issue(0); CP_COMMIT();
    issue(1); CP_COMMIT();

    for (int g = 0; g < nch; g++) {
        const int s = g % 3;
        CP_WAIT1();                                 // chunk g landed
        __syncthreads();                            // chunk g-1 fully consumed by all warps
        issue(g + 2);                               // may belong to the next tile
        CP_COMMIT();

        const uint32_t sA = sb + s * STAGE;
        const uint32_t sB = sA + A_BYTES;
#pragma unroll
        for (int ks = 0; ks < 4; ks++) {            // 4 x k16 steps, +32B each
            const int kb = ks * 32;
            uint32_t a[MI][4], b[8][2];
#pragma unroll
            for (int mi = 0; mi < MI; mi++)
                LDSM_X4(a[mi][0], a[mi][1], a[mi][2], a[mi][3], sA + offA[mi] + kb);
#pragma unroll
            for (int p = 0; p < 4; p++)
                LDSM_X4(b[2 * p][0], b[2 * p][1], b[2 * p + 1][0], b[2 * p + 1][1],
                        sB + offB[p] + kb);
#pragma unroll
            for (int mi = 0; mi < MI; mi++)
#pragma unroll
                for (int ni = 0; ni < 8; ni++)
                    mma_f16(acc[mi][ni], a[mi], b[ni]);
        }

        // tile finished? -> epilogue (no smem; overlaps next tile's cp.async)
        if ((g % KCH) == KCH - 1) {
            const int t  = blockIdx.x + (g / KCH) * gridDim.x;
            const int bm = (t / NTX) * BM;
            const int bn = (t % NTX) * BN;
#pragma unroll
            for (int ni = 0; ni < 8; ni++) {
                const int n = bn + wn * 64 + ni * 8 + tig * 2;
                const float bv0 = __ldg(&bias[n]);
                const float bv1 = __ldg(&bias[n + 1]);
#pragma unroll
                for (int mi = 0; mi < MI; mi++) {
                    const int m0 = bm + wm * 32 + mi * 16 + grp;
                    float v0 = acc[mi][ni][0] + bv0;
                    float v1 = acc[mi][ni][1] + bv1;
                    float v2 = acc[mi][ni][2] + bv0;
                    float v3 = acc[mi][ni][3] + bv1;
                    if (RELU) {
                        v0 = fmaxf(v0, 0.0f); v1 = fmaxf(v1, 0.0f);
                        v2 = fmaxf(v2, 0.0f); v3 = fmaxf(v3, 0.0f);
                    }
                    if (HALF_OUT) {
                        __half* C = (__half*)Cv;
                        *(__half2*)(C + (size_t)m0 * N_TOTAL + n)       = __floats2half2_rn(v0, v1);
                        *(__half2*)(C + (size_t)(m0 + 8) * N_TOTAL + n) = __floats2half2_rn(v2, v3);
                    } else {
                        float* C = (float*)Cv;
                        *(float2*)(C + (size_t)m0 * N_TOTAL + n)       = make_float2(v0, v1);
                        *(float2*)(C + (size_t)(m0 + 8) * N_TOTAL + n) = make_float2(v2, v3);
                    }
                    acc[mi][ni][0] = 0.0f; acc[mi][ni][1] = 0.0f;
                    acc[mi][ni][2] = 0.0f; acc[mi][ni][3] = 0.0f;
                }
            }
        }
    }
}

// ---------------- merged prep kernel ----------------
// blocks [0, GB): gather emb[tok] -> fp16 x            (2 float4 per thread)
// blocks [GB, GB+256): cvt conv_w -> w0
// blocks [GB+256, GB+768): transpose+cvt w1 -> w1t
// blocks [GB+768, GB+896): transpose+cvt w2 -> w2t
#define GATHER_BLOCKS (M_TOTAL * EMBED / 8 / 256)   // 8192
__global__ __launch_bounds__(256)
void prep_kernel(const int* __restrict__ tok, const float* __restrict__ emb,
                 __half* __restrict__ x,
                 const float* __restrict__ conv_w, __half* __restrict__ w0,
                 const float* __restrict__ w1, __half* __restrict__ w1t,
                 const float* __restrict__ w2, __half* __restrict__ w2t) {
    const int b = blockIdx.x;
    const int tid = threadIdx.x;
    if (b < GATHER_BLOCKS) {
        const int base = (b * 256 + tid) * 2;
#pragma unroll
        for (int u = 0; u < 2; u++) {
            const int i4 = base + u;
            const int row = i4 >> 7;                // EMBED/4 = 128
            const int c   = (i4 & 127) << 2;
            const float4 v = *(const float4*)(emb + (size_t)tok[row] * EMBED + c);
            __half2 h0 = __floats2half2_rn(v.x, v.y);
            __half2 h1 = __floats2half2_rn(v.z, v.w);
            *(uint2*)(x + (size_t)row * EMBED + c) = make_uint2(*(uint32_t*)&h0, *(uint32_t*)&h1);
        }
        return;
    }
    const int wb = b - GATHER_BLOCKS;
    if (wb < 256) {                                 // cvt conv_w
        const int i4 = wb * 256 + tid;
        const float4 v = *(const float4*)(conv_w + (size_t)i4 * 4);
        __half2 h0 = __floats2half2_rn(v.x, v.y);
        __half2 h1 = __floats2half2_rn(v.z, v.w);
        *(uint2*)(w0 + (size_t)i4 * 4) = make_uint2(*(uint32_t*)&h0, *(uint32_t*)&h1);
        return;
    }
    const float* in; __half* outp; int R, Ccols, tb;
    if (wb < 768) { in = w1; outp = w1t; R = CONVC; Ccols = HID;    tb = wb - 256; }
    else          { in = w2; outp = w2t; R = HID;   Ccols = LABELS; tb = wb - 768; }
    const int tpr = Ccols / 32;
    const int by = (tb / tpr) * 32, bx = (tb % tpr) * 32;
    const int tx = tid & 31, ty = tid >> 5;
    __shared__ float t[32][33];
    int x2 = bx + tx;
#pragma unroll
    for (int jj = 0; jj < 32; jj += 8) {
        int y = by + ty + jj;
        t[ty + jj][tx] = in[(size_t)y * Ccols + x2];
    }
    __syncthreads();
    x2 = by + tx;
#pragma unroll
    for (int jj = 0; jj < 32; jj += 8) {
        int y = bx + ty + jj;
        outp[(size_t)y * R + x2] = __float2half_rn(t[tx][ty + jj]);
    }
}

extern "C" void kernel_launch(void* const* d_in, const int* in_sizes, int n_in,
                              void* d_out, int out_size) {
    const int*   tok    = (const int*)d_in[0];
    const float* emb    = (const float*)d_in[1];
    const float* conv_w = (const float*)d_in[2];   // [CONVC, EMBED] = [N,K]
    const float* conv_b = (const float*)d_in[3];
    const float* w1     = (const float*)d_in[4];   // [CONVC, HID]
    const float* b1     = (const float*)d_in[5];
    const float* w2     = (const float*)d_in[6];   // [HID, LABELS]
    const float* b2     = (const float*)d_in[7];
    float* out = (float*)d_out;

    __half *x_buf, *h_buf, *z_buf, *w0, *w1t, *w2t;
    cudaGetSymbolAddress((void**)&x_buf, g_x);
    cudaGetSymbolAddress((void**)&h_buf, g_h);
    cudaGetSymbolAddress((void**)&z_buf, g_z);
    cudaGetSymbolAddress((void**)&w0,  g_w0);
    cudaGetSymbolAddress((void**)&w1t, g_w1t);
    cudaGetSymbolAddress((void**)&w2t, g_w2t);

    constexpr int SMEM = 3 * (128 * 144 + 128 * 144);   // 110592 -> 2 CTAs/SM
    cudaFuncSetAttribute(gemm_pipe_h<CONVC, EMBED, true,  true>,
                         cudaFuncAttributeMaxDynamicSharedMemorySize, SMEM);
    cudaFuncSetAttribute(gemm_pipe_h<HID, CONVC, true,  true>,
                         cudaFuncAttributeMaxDynamicSharedMemorySize, SMEM);
    cudaFuncSetAttribute(gemm_pipe_h<LABELS, HID, false, false>,
                         cudaFuncAttributeMaxDynamicSharedMemorySize, SMEM);

    constexpr int PERSIST = 296;                    // 148 SMs x 2 CTAs

    // Prep (one kernel: gather + all weight conversions)
    prep_kernel<<<GATHER_BLOCKS + 896, 256>>>(tok, emb, x_buf, conv_w, w0, w1, w1t, w2, w2t);

    // GEMM1: h = fp16(relu(x @ conv_w^T + conv_b))    [32768, 512], 1024 tiles
    gemm_pipe_h<CONVC, EMBED, true, true>
        <<<PERSIST, 256, SMEM>>>(x_buf, w0, conv_b, h_buf);
    // GEMM2: z = fp16(relu(h @ w1 + b1))              [32768, 1024], 2048 tiles
    gemm_pipe_h<HID, CONVC, true, true>
        <<<PERSIST, 256, SMEM>>>(h_buf, w1t, b1, z_buf);
    // GEMM3: out = z @ w2 + b2                        [32768, 128], 256 tiles
    gemm_pipe_h<LABELS, HID, false, false>
        <<<256, 256, SMEM>>>(z_buf, w2t, b2, out);
}